// round 3
// baseline (speedup 1.0000x reference)
#include <cuda_runtime.h>

// preds: [16,8,17,128,128] f32 -> N=128, K=17, H=W=128
// gt:    [16,8,10,17,2]    f32 -> [N=128, P=10, K=17, 2]
// out:   2 floats (total_within, total_across)
#define N_TOT 128
#define P_NUM 10
#define K_NUM 17
#define HH 128
#define WW 128
#define INV_STRIDE 0.25f
#define NTHREADS 192

__device__ float g_acc_w = 0.0f;
__device__ float g_acc_a = 0.0f;
__device__ int   g_count = 0;

__global__ void __launch_bounds__(NTHREADS, 8)
group_loss_kernel(const float* __restrict__ preds,
                  const float* __restrict__ gt,
                  float* __restrict__ out) {
    const int n = blockIdx.x;
    const int t = threadIdx.x;

    __shared__ float s_val[P_NUM][K_NUM];
    __shared__ float s_msk[P_NUM][K_NUM];
    __shared__ float s_embed[P_NUM];
    __shared__ float s_pv[P_NUM];
    __shared__ float s_wp[P_NUM];
    __shared__ int   s_last;

    if (t == 0) s_last = 0;

    // ---- Stage 1: gather (one scattered preds load per active thread) ----
    if (t < P_NUM * K_NUM) {
        const int p = t / K_NUM;
        const int k = t % K_NUM;
        const float2 g = __ldg((const float2*)gt + (n * P_NUM + p) * K_NUM + k);
        const int x = (int)rintf(g.x * INV_STRIDE);   // jnp.round = round-half-even = rintf
        const int y = (int)rintf(g.y * INV_STRIDE);
        const bool valid = (x >= 0) && (x < WW) && (y >= 0) && (y < HH);
        const int xc = min(max(x, 0), WW - 1);
        const int yc = min(max(y, 0), HH - 1);
        const float v = __ldg(&preds[((n * K_NUM + k) * HH + yc) * WW + xc]);
        s_val[p][k] = valid ? v : 0.0f;
        s_msk[p][k] = valid ? 1.0f : 0.0f;
    }
    __syncthreads();

    // ---- Stage 2: per-person moments, single pass (threads 0..9) ----
    if (t < P_NUM) {
        float sum = 0.0f, sumsq = 0.0f, cnt = 0.0f;
#pragma unroll
        for (int k = 0; k < K_NUM; k++) {
            const float v = s_val[t][k];
            sum   += v;
            sumsq += v * v;       // masked-out entries already 0
            cnt   += s_msk[t][k];
        }
        const float safe = fmaxf(cnt, 1.0f);
        const float e = sum / safe;
        // Σ(v-e)²·m = Σv²m − 2e·Σvm + e²·cnt
        float w = (sumsq - 2.0f * e * sum + e * e * cnt) / safe;
        if (!(cnt > 0.0f)) w = 0.0f;
        s_embed[t] = e;
        s_pv[t]    = (cnt > 0.0f) ? 1.0f : 0.0f;
        s_wp[t]    = w;
    }
    __syncthreads();

    // ---- Stage 3: warp 0 — each thread t<10 owns row i=t of the ordered
    //      pairwise sum (j != i). No unranking, no symmetry factor. ----
    if (t < 32) {
        float hs = 0.0f, dn = 0.0f, within = 0.0f;
        if (t < P_NUM) {
            within = s_wp[t];
            const float pvi = s_pv[t];
            const float ei  = s_embed[t];
#pragma unroll
            for (int j = 0; j < P_NUM; j++) {
                if (j == t) continue;
                const float pair = pvi * s_pv[j];
                const float d = fabsf(s_embed[j] - ei);
                hs += fmaxf(1.0f - d, 0.0f) * pair;
                dn += pair;
            }
        }
#pragma unroll
        for (int o = 16; o > 0; o >>= 1) {
            hs     += __shfl_down_sync(0xFFFFFFFFu, hs, o);
            dn     += __shfl_down_sync(0xFFFFFFFFu, dn, o);
            within += __shfl_down_sync(0xFFFFFFFFu, within, o);
        }
        if (t == 0) {
            const float across = (dn > 0.0f) ? (hs / fmaxf(dn, 1.0f)) : 0.0f;
            within *= (1.0f / (float)P_NUM);
            atomicAdd(&g_acc_w, within);
            atomicAdd(&g_acc_a, across);
            __threadfence();
            const int done = atomicAdd(&g_count, 1);
            if (done == N_TOT - 1) s_last = 1;
        }
    }
    __syncthreads();

    // ---- Stage 4: last block finalizes and resets for next graph replay ----
    if (t == 0 && s_last) {
        __threadfence();
        const float W = g_acc_w;
        const float A = g_acc_a;
        g_acc_w = 0.0f;
        g_acc_a = 0.0f;
        g_count = 0;
        out[0] = W * (1.0f / (float)N_TOT);
        out[1] = A * (1.0f / (float)N_TOT);
    }
}

extern "C" void kernel_launch(void* const* d_in, const int* in_sizes, int n_in,
                              void* d_out, int out_size) {
    const float* preds = (const float*)d_in[0];
    const float* gt    = (const float*)d_in[1];
    float* out = (float*)d_out;
    group_loss_kernel<<<N_TOT, NTHREADS>>>(preds, gt, out);
}

// round 6
// speedup vs baseline: 1.0515x; 1.0515x over previous
#include <cuda_runtime.h>

// preds: [16,8,17,128,128] f32 -> N=128, K=17, H=W=128
// gt:    [16,8,10,17,2]    f32 -> [N=128, P=10, K=17, 2]
// out:   2 floats (total_within, total_across)
#define N_TOT 128
#define P_NUM 10
#define K_NUM 17
#define HH 128
#define WW 128
#define INV_STRIDE 0.25f
#define NTHREADS 192

__device__ float g_acc_w = 0.0f;
__device__ float g_acc_a = 0.0f;
__device__ int   g_count = 0;

__global__ void __launch_bounds__(NTHREADS, 8)
group_loss_kernel(const float* __restrict__ preds,
                  const float* __restrict__ gt,
                  float* __restrict__ out) {
    const int n = blockIdx.x;
    const int t = threadIdx.x;

    __shared__ float s_val[P_NUM][K_NUM];
    __shared__ float s_msk[P_NUM][K_NUM];
    __shared__ float s_embed[P_NUM];
    __shared__ float s_pv[P_NUM];
    __shared__ float s_wp[P_NUM];

    // ---- Stage 1: gather; 170 independent scattered loads across 6 warps ----
    if (t < P_NUM * K_NUM) {
        const int p = t / K_NUM;
        const int k = t - p * K_NUM;
        const float2 g = __ldg((const float2*)gt + (n * P_NUM + p) * K_NUM + k);
        const int x = (int)rintf(g.x * INV_STRIDE);   // jnp.round = round-half-even = rintf
        const int y = (int)rintf(g.y * INV_STRIDE);
        const bool valid = (x >= 0) && (x < WW) && (y >= 0) && (y < HH);
        const int xc = min(max(x, 0), WW - 1);
        const int yc = min(max(y, 0), HH - 1);
        const float v = __ldg(&preds[((n * K_NUM + k) * HH + yc) * WW + xc]);
        s_val[p][k] = valid ? v : 0.0f;
        s_msk[p][k] = valid ? 1.0f : 0.0f;
    }
    __syncthreads();

    // ---- Stages 2-4 run entirely on warp 0 (threads 0..31) ----
    if (t < 32) {
        // Stage 2: per-person moments, single pass (lanes 0..9)
        if (t < P_NUM) {
            float sum = 0.0f, sumsq = 0.0f, cnt = 0.0f;
#pragma unroll
            for (int k = 0; k < K_NUM; k++) {
                const float v = s_val[t][k];
                sum   += v;
                sumsq += v * v;       // masked-out entries already 0
                cnt   += s_msk[t][k];
            }
            const float safe = fmaxf(cnt, 1.0f);
            const float e = sum / safe;
            // Σ(v-e)²·m = Σv²m − 2e·Σvm + e²·cnt
            float w = (sumsq - 2.0f * e * sum + e * e * cnt) / safe;
            if (!(cnt > 0.0f)) w = 0.0f;
            s_embed[t] = e;
            s_pv[t]    = (cnt > 0.0f) ? 1.0f : 0.0f;
            s_wp[t]    = w;
        }
        __syncwarp();  // cross-lane smem handoff within warp 0 only

        // Stage 3: lane i<10 owns ordered row i of the pairwise hinge sum
        float hs = 0.0f, dn = 0.0f, within = 0.0f;
        if (t < P_NUM) {
            within = s_wp[t];
            const float pvi = s_pv[t];
            const float ei  = s_embed[t];
#pragma unroll
            for (int j = 0; j < P_NUM; j++) {
                const float self = (j == t) ? 0.0f : 1.0f;  // branchless diag mask
                const float pair = pvi * s_pv[j] * self;
                const float d = fabsf(s_embed[j] - ei);
                hs += fmaxf(1.0f - d, 0.0f) * pair;
                dn += pair;
            }
        }
        // contributing lanes are 0..9 -> reduction starts at offset 8
#pragma unroll
        for (int o = 8; o > 0; o >>= 1) {
            hs     += __shfl_down_sync(0xFFFFFFFFu, hs, o);
            dn     += __shfl_down_sync(0xFFFFFFFFu, dn, o);
            within += __shfl_down_sync(0xFFFFFFFFu, within, o);
        }
        if (t == 0) {
            const float across = (dn > 0.0f) ? (hs / fmaxf(dn, 1.0f)) : 0.0f;
            within *= (1.0f / (float)P_NUM);
            atomicAdd(&g_acc_w, within);
            atomicAdd(&g_acc_a, across);
            __threadfence();   // release g_acc_* before the count increment
            const int done = atomicAdd(&g_count, 1);
            if (done == N_TOT - 1) {
                __threadfence();  // acquire all blocks' g_acc_* writes
                const float W = g_acc_w;
                const float A = g_acc_a;
                g_acc_w = 0.0f;
                g_acc_a = 0.0f;
                g_count = 0;
                out[0] = W * (1.0f / (float)N_TOT);
                out[1] = A * (1.0f / (float)N_TOT);
            }
        }
    }
}

extern "C" void kernel_launch(void* const* d_in, const int* in_sizes, int n_in,
                              void* d_out, int out_size) {
    const float* preds = (const float*)d_in[0];
    const float* gt    = (const float*)d_in[1];
    float* out = (float*)d_out;
    group_loss_kernel<<<N_TOT, NTHREADS>>>(preds, gt, out);
}